// round 16
// baseline (speedup 1.0000x reference)
#include <cuda_runtime.h>
#include <cuda_fp16.h>

// Problem constants: B=32, C=3, H=W=512
#define Bv 32
#define Cv 3
#define Hv 512
#define Wv 512
#define PLANE (Hv*Wv)            // 262144
#define NPLANES (Bv*Cv)          // 96
#define K1B 32                   // K1 blocks per plane (one partial each)
#define RSTRIP 8                 // output rows per K2 block (64 strips/plane)
#define PCHUNK 24                // planes per pipeline chunk (4 chunks)
#define NCHUNK (NPLANES / PCHUNK)
#define PFD 3                    // K2 prefetch depth (rows in flight)

// Deterministic partial sums (no atomics): one slot per (plane, k1-block)
__device__ float d_partial[NPLANES * K1B];
// Double-buffered fp16 scratch: y = x^gamma for one chunk per buffer (12.6 MB
// each). K1(c+1) fills buffer (c+1)&1 WHILE K2(c) drains buffer c&1.
__device__ __half d_scratch[2][(size_t)PCHUNK * PLANE];

__device__ __forceinline__ float fast_pow(float x, float g) {
    return __powf(x, g);         // MUFU.LG2 + FMUL + MUFU.EX2 ; 0^g -> 0 correct
}

// ---------------- K1 body: pow + plane-sum partial + fp16 scratch ----------------
// 128 threads; block xb covers 2048 float4 of plane `plane`.
__device__ __forceinline__ void k1_body(const float* __restrict__ x,
                                        const float* __restrict__ gamma,
                                        int plane, int lplane, int buf,
                                        int xb, int tid) {
    const int b = plane / Cv;
    const float g = __ldg(&gamma[b]);
    const float4* px = (const float4*)(x + (size_t)plane * PLANE);
    uint2* pu = (uint2*)(d_scratch[buf] + (size_t)lplane * PLANE);

    float s0 = 0.f, s1 = 0.f, s2 = 0.f, s3 = 0.f;
    const int base = xb * 2048 + tid;
#pragma unroll 4
    for (int k = 0; k < 16; k++) {
        int idx = base + k * 128;
        float4 v = px[idx];
        float y0 = fast_pow(v.x, g);
        float y1 = fast_pow(v.y, g);
        float y2 = fast_pow(v.z, g);
        float y3 = fast_pow(v.w, g);
        s0 += y0; s1 += y1; s2 += y2; s3 += y3;
        __half2 h01 = __floats2half2_rn(y0, y1);
        __half2 h23 = __floats2half2_rn(y2, y3);
        uint2 u;
        u.x = *reinterpret_cast<unsigned*>(&h01);
        u.y = *reinterpret_cast<unsigned*>(&h23);
        pu[idx] = u;
    }
    float s = (s0 + s1) + (s2 + s3);
#pragma unroll
    for (int o = 16; o; o >>= 1) s += __shfl_xor_sync(0xFFFFFFFFu, s, o);

    __shared__ float ws[4];
    int lane = tid & 31, w = tid >> 5;
    if (lane == 0) ws[w] = s;
    __syncthreads();
    if (tid == 0)
        d_partial[plane * K1B + xb] = (ws[0] + ws[1]) + (ws[2] + ws[3]);
}

// ---------------- K2 conv body: rolling register pipeline over scratch ----------------
template <bool INTERIOR>
__device__ __forceinline__ void k2_conv(const __half* __restrict__ psc,
                                        float* __restrict__ po,
                                        int y0, int tid, int lane,
                                        float wct, float beta, float s) {
    const int cbase = (tid >> 5) * 128;      // warp's first column
    const bool evL = (lane == 0)  && (cbase > 0);
    const bool evR = (lane == 31) && (cbase + 128 < Wv);
    const int eoff = evL ? (cbase - 1) : (cbase + 128);
    const bool ev  = evL || evR;

    float rs0[4] = {0.f, 0.f, 0.f, 0.f};
    float rs1[4] = {0.f, 0.f, 0.f, 0.f};
    float ctr[4] = {0.f, 0.f, 0.f, 0.f};

    uint2 vbuf[PFD];
    float ebuf[PFD];

#pragma unroll
    for (int k = 0; k < PFD; k++) {
        int gy = y0 - 1 + k;
        vbuf[k] = make_uint2(0u, 0u);
        ebuf[k] = 0.f;
        if ((INTERIOR || (unsigned)gy < (unsigned)Hv) && k < RSTRIP + 2) {
            vbuf[k] = ((const uint2*)(psc + gy * Wv))[tid];
            if (ev) ebuf[k] = __half2float(psc[gy * Wv + eoff]);
        }
    }

#pragma unroll
    for (int i = 0; i < RSTRIP + 2; i++) {
        const int gy = y0 - 1 + i;
        uint2 rv = vbuf[i % PFD];
        float eyv = ebuf[i % PFD];

        if (i + PFD < RSTRIP + 2) {
            const int gyp = gy + PFD;
            uint2 vp = make_uint2(0u, 0u);
            float ep = 0.f;
            if (INTERIOR || gyp < Hv) {
                vp = ((const uint2*)(psc + gyp * Wv))[tid];
                if (ev) ep = __half2float(psc[gyp * Wv + eoff]);
            }
            vbuf[i % PFD] = vp;
            ebuf[i % PFD] = ep;
        }

        __half2 h01 = *reinterpret_cast<__half2*>(&rv.x);
        __half2 h23 = *reinterpret_cast<__half2*>(&rv.y);
        float2 f01 = __half22float2(h01);
        float2 f23 = __half22float2(h23);
        float f0 = __saturatef(fmaf(f01.x, wct, beta));
        float f1 = __saturatef(fmaf(f01.y, wct, beta));
        float f2 = __saturatef(fmaf(f23.x, wct, beta));
        float f3 = __saturatef(fmaf(f23.y, wct, beta));
        float e  = __saturatef(fmaf(eyv,  wct, beta));
        if (!INTERIOR) {
            const bool vval = (unsigned)gy < (unsigned)Hv;
            if (!vval) { f0 = f1 = f2 = f3 = 0.f; }
            if (!(vval && ev)) e = 0.f;
        } else {
            if (!ev) e = 0.f;
        }

        float fl = __shfl_up_sync(0xFFFFFFFFu, f3, 1);
        if (lane == 0) fl = e;
        float fr = __shfl_down_sync(0xFFFFFFFFu, f0, 1);
        if (lane == 31) fr = e;

        float rs2_0 = fl + f0 + f1;
        float rs2_1 = f0 + f1 + f2;
        float rs2_2 = f1 + f2 + f3;
        float rs2_3 = f2 + f3 + fr;

        if (i >= 2) {
            float4 o4;
            float s9, c;
            c = ctr[0]; s9 = rs0[0] + rs1[0] + rs2_0;
            o4.x = __saturatef(fmaf(s, fmaf(9.f, c, -s9), c));
            c = ctr[1]; s9 = rs0[1] + rs1[1] + rs2_1;
            o4.y = __saturatef(fmaf(s, fmaf(9.f, c, -s9), c));
            c = ctr[2]; s9 = rs0[2] + rs1[2] + rs2_2;
            o4.z = __saturatef(fmaf(s, fmaf(9.f, c, -s9), c));
            c = ctr[3]; s9 = rs0[3] + rs1[3] + rs2_3;
            o4.w = __saturatef(fmaf(s, fmaf(9.f, c, -s9), c));
            __stcs(((float4*)(po + (gy - 1) * Wv)) + tid, o4);
        }

        rs0[0] = rs1[0]; rs0[1] = rs1[1]; rs0[2] = rs1[2]; rs0[3] = rs1[3];
        rs1[0] = rs2_0;  rs1[1] = rs2_1;  rs1[2] = rs2_2;  rs1[3] = rs2_3;
        ctr[0] = f0; ctr[1] = f1; ctr[2] = f2; ctr[3] = f3;
    }
}

// ---------------- K2 body: mean fold + conv dispatch ----------------
__device__ __forceinline__ void k2_body(const float* __restrict__ wb,
                                        const float* __restrict__ contrast,
                                        const float* __restrict__ sharpen,
                                        float* __restrict__ out,
                                        int plane, int lplane, int buf,
                                        int strip, int tid) {
    const int b = plane / Cv;
    const float w  = __ldg(&wb[plane]);
    const float ct = __ldg(&contrast[b]);
    const float s  = __ldg(&sharpen[b]);
    const float wct = w * ct;

    __shared__ float s_beta;
    const int lane = tid & 31;

    if (tid < 32) {
        float p = d_partial[plane * K1B + tid];
#pragma unroll
        for (int o = 16; o; o >>= 1) p += __shfl_xor_sync(0xFFFFFFFFu, p, o);
        if (tid == 0) {
            float mean = p * w * (1.0f / (float)PLANE);
            s_beta = mean - mean * ct;       // mean*(1-contrast)
        }
    }
    __syncthreads();
    const float beta = s_beta;

    const __half* __restrict__ psc = d_scratch[buf] + (size_t)lplane * PLANE;
    float* __restrict__ po = out + (size_t)plane * PLANE;
    const int y0 = strip * RSTRIP;

    if (y0 >= RSTRIP && y0 + RSTRIP < Hv)
        k2_conv<true>(psc, po, y0, tid, lane, wct, beta, s);
    else
        k2_conv<false>(psc, po, y0, tid, lane, wct, beta, s);
}

// ---------------- Kernels ----------------
__global__ void __launch_bounds__(128) k1_only(const float* __restrict__ x,
                                               const float* __restrict__ gamma,
                                               int p0, int buf) {
    k1_body(x, gamma, p0 + blockIdx.y, blockIdx.y, buf, blockIdx.x, threadIdx.x);
}

__global__ void __launch_bounds__(128) k2_only(const float* __restrict__ wb,
                                               const float* __restrict__ contrast,
                                               const float* __restrict__ sharpen,
                                               float* __restrict__ out,
                                               int p0, int buf) {
    k2_body(wb, contrast, sharpen, out, p0 + blockIdx.y, blockIdx.y, buf,
            blockIdx.x, threadIdx.x);
}

// Combined: blockIdx.x in [0,64) -> K2 strip of chunk A (buffer bufA);
//           blockIdx.x in [64,96) -> K1 block of chunk B (buffer bufB).
// x-major block order interleaves BW-bound K1 blocks with latency-bound K2
// blocks in every wave -> the two pipelines fill each other's stalls.
__global__ void __launch_bounds__(128) k_comb(const float* __restrict__ x,
                                              const float* __restrict__ gamma,
                                              const float* __restrict__ wb,
                                              const float* __restrict__ contrast,
                                              const float* __restrict__ sharpen,
                                              float* __restrict__ out,
                                              int p0A, int bufA,
                                              int p0B, int bufB) {
    if (blockIdx.x < 64) {
        k2_body(wb, contrast, sharpen, out, p0A + blockIdx.y, blockIdx.y, bufA,
                blockIdx.x, threadIdx.x);
    } else {
        k1_body(x, gamma, p0B + blockIdx.y, blockIdx.y, bufB,
                blockIdx.x - 64, threadIdx.x);
    }
}

extern "C" void kernel_launch(void* const* d_in, const int* in_sizes, int n_in,
                              void* d_out, int out_size) {
    const float* x        = (const float*)d_in[0];
    const float* gamma    = (const float*)d_in[1];
    const float* wb       = (const float*)d_in[2];
    const float* contrast = (const float*)d_in[3];
    const float* sharpen  = (const float*)d_in[4];
    float* out = (float*)d_out;

    // Software pipeline: K1(0); [K2(c) || K1(c+1)] x3; K2(last).
    // Double-buffered scratch makes each combined pair independent.
    k1_only<<<dim3(K1B, PCHUNK), 128>>>(x, gamma, 0, 0);
    for (int c = 0; c < NCHUNK; c++) {
        if (c + 1 < NCHUNK) {
            k_comb<<<dim3(96, PCHUNK), 128>>>(x, gamma, wb, contrast, sharpen,
                                              out,
                                              c * PCHUNK, c & 1,
                                              (c + 1) * PCHUNK, (c + 1) & 1);
        } else {
            k2_only<<<dim3(64, PCHUNK), 128>>>(wb, contrast, sharpen, out,
                                               c * PCHUNK, c & 1);
        }
    }
}

// round 17
// speedup vs baseline: 1.0404x; 1.0404x over previous
#include <cuda_runtime.h>
#include <cuda_fp16.h>

// Problem constants: B=32, C=3, H=W=512
#define Bv 32
#define Cv 3
#define Hv 512
#define Wv 512
#define PLANE (Hv*Wv)            // 262144
#define NPLANES (Bv*Cv)          // 96
#define K1_BLOCKS_PER_PLANE 32
#define RSTRIP 8                 // output rows per K2 block (64 strips/plane)
#define PCHUNK 48                // planes per pipeline chunk
#define PFD 3                    // K2 prefetch depth (rows in flight)

// Deterministic partial sums (no atomics): one slot per (plane, block)
__device__ float d_partial[NPLANES * K1_BLOCKS_PER_PLANE];
// fp16 scratch holding y = x^gamma for ONE chunk (24 MB, reused per chunk,
// stays L2-hot: written by K1(c), consumed by K2(c), overwritten by K1(c+1))
__device__ __half d_scratch[(size_t)PCHUNK * PLANE];

__device__ __forceinline__ float fast_pow(float x, float g) {
    return __powf(x, g);         // MUFU.LG2 + FMUL + MUFU.EX2 ; 0^g -> 0 correct
}

// ---------------- Kernel 1: per-plane sum of x^gamma + fp16 y scratch ----------------
// x reads are STREAMING (__ldcs): x is consumed exactly once; evict-first
// keeps the 25 MB of dead x lines from displacing the scratch this kernel
// just wrote (K2 needs the scratch L2-resident).
__global__ void __launch_bounds__(256) k1_pow_sum(const float* __restrict__ x,
                                                 const float* __restrict__ gamma,
                                                 int plane0) {
    const int plane = plane0 + blockIdx.y;   // global plane b*3 + c
    const int b = plane / Cv;
    const float g = __ldg(&gamma[b]);
    const float4* px = (const float4*)(x + (size_t)plane * PLANE);
    uint2* pu = (uint2*)(d_scratch + (size_t)blockIdx.y * PLANE);  // local plane

    float s0 = 0.f, s1 = 0.f, s2 = 0.f, s3 = 0.f;
    int base = blockIdx.x * 2048 + threadIdx.x;   // 2048 float4 per block
#pragma unroll
    for (int k = 0; k < 8; k++) {
        int idx = base + k * 256;
        float4 v = __ldcs(px + idx);
        float y0 = fast_pow(v.x, g);
        float y1 = fast_pow(v.y, g);
        float y2 = fast_pow(v.z, g);
        float y3 = fast_pow(v.w, g);
        s0 += y0; s1 += y1; s2 += y2; s3 += y3;
        __half2 h01 = __floats2half2_rn(y0, y1);
        __half2 h23 = __floats2half2_rn(y2, y3);
        uint2 u;
        u.x = *reinterpret_cast<unsigned*>(&h01);
        u.y = *reinterpret_cast<unsigned*>(&h23);
        pu[idx] = u;
    }
    float s = (s0 + s1) + (s2 + s3);
#pragma unroll
    for (int o = 16; o; o >>= 1) s += __shfl_xor_sync(0xFFFFFFFFu, s, o);

    __shared__ float ws[8];
    int lane = threadIdx.x & 31, w = threadIdx.x >> 5;
    if (lane == 0) ws[w] = s;
    __syncthreads();
    if (w == 0) {
        s = (lane < 8) ? ws[lane] : 0.f;
#pragma unroll
        for (int o = 4; o; o >>= 1) s += __shfl_xor_sync(0xFFFFFFFFu, s, o);
        if (lane == 0) d_partial[plane * K1_BLOCKS_PER_PLANE + blockIdx.x] = s;
    }
}

// ---------------- Kernel 2 body: conv pipeline reading fp16 scratch ----------------
// Thread t owns output columns 4t..4t+3. Walks RSTRIP+2 scratch rows (8B/row
// per thread) with depth-PFD prefetch; horizontal halo via shuffles + 2
// predicated scalar loads at warp edges. No pow, no MUFU. Scratch reads use
// DEFAULT policy (each line is read twice: interior + neighbor-strip halo);
// out stores stream (__stcs).
template <bool INTERIOR>
__device__ __forceinline__ void k2_body(const __half* __restrict__ psc,
                                        float* __restrict__ po,
                                        int y0, int tid, int lane,
                                        float wct, float beta, float s) {
    const int cbase = (tid >> 5) * 128;      // warp's first column
    const bool evL = (lane == 0)  && (cbase > 0);
    const bool evR = (lane == 31) && (cbase + 128 < Wv);
    const int eoff = evL ? (cbase - 1) : (cbase + 128);
    const bool ev  = evL || evR;

    float rs0[4] = {0.f, 0.f, 0.f, 0.f};
    float rs1[4] = {0.f, 0.f, 0.f, 0.f};
    float ctr[4] = {0.f, 0.f, 0.f, 0.f};

    uint2 vbuf[PFD];
    float ebuf[PFD];

    // Prologue: prefetch rows y0-1 .. y0-1+PFD-1
#pragma unroll
    for (int k = 0; k < PFD; k++) {
        int gy = y0 - 1 + k;
        vbuf[k] = make_uint2(0u, 0u);
        ebuf[k] = 0.f;
        if ((INTERIOR || (unsigned)gy < (unsigned)Hv) && k < RSTRIP + 2) {
            vbuf[k] = ((const uint2*)(psc + gy * Wv))[tid];
            if (ev) ebuf[k] = __half2float(psc[gy * Wv + eoff]);
        }
    }

#pragma unroll
    for (int i = 0; i < RSTRIP + 2; i++) {
        const int gy = y0 - 1 + i;
        uint2 rv = vbuf[i % PFD];
        float eyv = ebuf[i % PFD];

        // Prefetch row gy+PFD into the slot just freed
        if (i + PFD < RSTRIP + 2) {
            const int gyp = gy + PFD;
            uint2 vp = make_uint2(0u, 0u);
            float ep = 0.f;
            if (INTERIOR || gyp < Hv) {
                vp = ((const uint2*)(psc + gyp * Wv))[tid];
                if (ev) ep = __half2float(psc[gyp * Wv + eoff]);
            }
            vbuf[i % PFD] = vp;
            ebuf[i % PFD] = ep;
        }

        // Unpack fp16 y and transform: f = sat(y*wct + beta) -> FFMA.SAT
        __half2 h01 = *reinterpret_cast<__half2*>(&rv.x);
        __half2 h23 = *reinterpret_cast<__half2*>(&rv.y);
        float2 f01 = __half22float2(h01);
        float2 f23 = __half22float2(h23);
        float f0 = __saturatef(fmaf(f01.x, wct, beta));
        float f1 = __saturatef(fmaf(f01.y, wct, beta));
        float f2 = __saturatef(fmaf(f23.x, wct, beta));
        float f3 = __saturatef(fmaf(f23.y, wct, beta));
        float e  = __saturatef(fmaf(eyv,  wct, beta));
        if (!INTERIOR) {
            const bool vval = (unsigned)gy < (unsigned)Hv;
            if (!vval) { f0 = f1 = f2 = f3 = 0.f; }
            if (!(vval && ev)) e = 0.f;
        } else {
            if (!ev) e = 0.f;
        }

        // Horizontal neighbors via shuffle (warp edges use e)
        float fl = __shfl_up_sync(0xFFFFFFFFu, f3, 1);
        if (lane == 0) fl = e;
        float fr = __shfl_down_sync(0xFFFFFFFFu, f0, 1);
        if (lane == 31) fr = e;

        float rs2_0 = fl + f0 + f1;
        float rs2_1 = f0 + f1 + f2;
        float rs2_2 = f1 + f2 + f3;
        float rs2_3 = f2 + f3 + fr;

        // Emit output row gy-1: out = sat(s*(9c - s9) + c)
        if (i >= 2) {
            float4 o4;
            float s9, c;

            c = ctr[0]; s9 = rs0[0] + rs1[0] + rs2_0;
            o4.x = __saturatef(fmaf(s, fmaf(9.f, c, -s9), c));

            c = ctr[1]; s9 = rs0[1] + rs1[1] + rs2_1;
            o4.y = __saturatef(fmaf(s, fmaf(9.f, c, -s9), c));

            c = ctr[2]; s9 = rs0[2] + rs1[2] + rs2_2;
            o4.z = __saturatef(fmaf(s, fmaf(9.f, c, -s9), c));

            c = ctr[3]; s9 = rs0[3] + rs1[3] + rs2_3;
            o4.w = __saturatef(fmaf(s, fmaf(9.f, c, -s9), c));

            __stcs(((float4*)(po + (gy - 1) * Wv)) + tid, o4);
        }

        // Rotate pipeline registers (renamed away by the full unroll)
        rs0[0] = rs1[0]; rs0[1] = rs1[1]; rs0[2] = rs1[2]; rs0[3] = rs1[3];
        rs1[0] = rs2_0;  rs1[1] = rs2_1;  rs1[2] = rs2_2;  rs1[3] = rs2_3;
        ctr[0] = f0; ctr[1] = f1; ctr[2] = f2; ctr[3] = f3;
    }
}

__global__ void __launch_bounds__(128) k2_main(const float* __restrict__ wb,
                                               const float* __restrict__ contrast,
                                               const float* __restrict__ sharpen,
                                               float* __restrict__ out,
                                               int plane0) {
    const int plane = plane0 + blockIdx.y;   // global plane
    const int b = plane / Cv;
    const float w  = __ldg(&wb[plane]);      // wb[b][c] flattens to wb[plane]
    const float ct = __ldg(&contrast[b]);
    const float s  = __ldg(&sharpen[b]);
    const float wct = w * ct;                // fold wb into contrast scale

    __shared__ float s_beta;
    const int tid  = threadIdx.x;
    const int lane = tid & 31;

    // Fold per-plane partials: warp 0, one load + shfl reduce.
    if (tid < 32) {
        float p = d_partial[plane * K1_BLOCKS_PER_PLANE + tid];
#pragma unroll
        for (int o = 16; o; o >>= 1) p += __shfl_xor_sync(0xFFFFFFFFu, p, o);
        if (tid == 0) {
            float mean = p * w * (1.0f / (float)PLANE);
            s_beta = mean - mean * ct;       // mean*(1-contrast)
        }
    }
    __syncthreads();
    const float beta = s_beta;

    const __half* __restrict__ psc = d_scratch + (size_t)blockIdx.y * PLANE;
    float* __restrict__ po = out + (size_t)plane * PLANE;
    const int y0 = blockIdx.x * RSTRIP;

    if (y0 >= RSTRIP && y0 + RSTRIP < Hv)
        k2_body<true>(psc, po, y0, tid, lane, wct, beta, s);
    else
        k2_body<false>(psc, po, y0, tid, lane, wct, beta, s);
}

extern "C" void kernel_launch(void* const* d_in, const int* in_sizes, int n_in,
                              void* d_out, int out_size) {
    const float* x        = (const float*)d_in[0];
    const float* gamma    = (const float*)d_in[1];
    const float* wb       = (const float*)d_in[2];
    const float* contrast = (const float*)d_in[3];
    const float* sharpen  = (const float*)d_in[4];
    float* out = (float*)d_out;

    // Pipeline by plane chunks: K1(c) computes sums AND fills the fp16 y
    // scratch; K2(c) consumes it while it is L2-hot. Same-stream ordering
    // guarantees K2(c) finishes before K1(c+1) overwrites the scratch.
    for (int p0 = 0; p0 < NPLANES; p0 += PCHUNK) {
        dim3 g1(K1_BLOCKS_PER_PLANE, PCHUNK);
        k1_pow_sum<<<g1, 256>>>(x, gamma, p0);
        dim3 g2(Hv / RSTRIP, PCHUNK);        // 64 strips x 48 planes = 3072 blocks
        k2_main<<<g2, 128>>>(wb, contrast, sharpen, out, p0);
    }
}